// round 4
// baseline (speedup 1.0000x reference)
#include <cuda_runtime.h>

#define BATCH 8
#define SEQ   4096
#define NTOK  (BATCH*SEQ)     // 32768
#define DIM   256
#define CWIN  5
#define KC    (CWIN*DIM)      // 1280

// ---- device scratch (static globals: allowed; no runtime allocation) ----
__device__ float g_a[(size_t)NTOK * DIM];   // relu(ctx@Wc1 + bc1), 33.5 MB
__device__ float g_Wfold[DIM * DIM];        // Wc2 @ Wr1[256:512]
__device__ float g_bfold[DIM];              // bc2 @ Wr1[256:512] + br1

// ---- tf32 helpers ----
__device__ __forceinline__ unsigned f2tf(float f) {
    unsigned u;
    asm("cvt.rna.tf32.f32 %0, %1;" : "=r"(u) : "f"(f));
    return u;
}

__device__ __forceinline__ void mma8(float* c, const unsigned* a, const unsigned* b) {
    asm volatile(
        "mma.sync.aligned.m16n8k8.row.col.f32.tf32.tf32.f32 "
        "{%0,%1,%2,%3}, {%4,%5,%6,%7}, {%8,%9}, {%0,%1,%2,%3};\n"
        : "+f"(c[0]), "+f"(c[1]), "+f"(c[2]), "+f"(c[3])
        : "r"(a[0]), "r"(a[1]), "r"(a[2]), "r"(a[3]), "r"(b[0]), "r"(b[1]));
}

// ============================================================
// Kernel 0: fold Wc2 into Wr1's h-half.
//   Wfold[k,j] = sum_r Wc2[k,r]*Wr1[256+r, j]
//   bfold[j]   = br1[j] + sum_r bc2[r]*Wr1[256+r, j]
// 4 independent accumulators -> 4-way ILP (was a 256-long FFMA chain).
// grid = 257 blocks x 256 threads (block 256 does the bias)
// ============================================================
__global__ void k_fold(const float* __restrict__ Wc2, const float* __restrict__ bc2,
                       const float* __restrict__ Wr1, const float* __restrict__ br1)
{
    int j = threadIdx.x;
    int k = blockIdx.x;
    float a0 = 0.f, a1 = 0.f, a2 = 0.f, a3 = 0.f;
    if (k < DIM) {
        #pragma unroll 4
        for (int r = 0; r < DIM; r += 4) {
            a0 = fmaf(Wc2[k*DIM + r  ], Wr1[(DIM + r  )*DIM + j], a0);
            a1 = fmaf(Wc2[k*DIM + r+1], Wr1[(DIM + r+1)*DIM + j], a1);
            a2 = fmaf(Wc2[k*DIM + r+2], Wr1[(DIM + r+2)*DIM + j], a2);
            a3 = fmaf(Wc2[k*DIM + r+3], Wr1[(DIM + r+3)*DIM + j], a3);
        }
        g_Wfold[k*DIM + j] = (a0 + a1) + (a2 + a3);
    } else {
        #pragma unroll 4
        for (int r = 0; r < DIM; r += 4) {
            a0 = fmaf(bc2[r  ], Wr1[(DIM + r  )*DIM + j], a0);
            a1 = fmaf(bc2[r+1], Wr1[(DIM + r+1)*DIM + j], a1);
            a2 = fmaf(bc2[r+2], Wr1[(DIM + r+2)*DIM + j], a2);
            a3 = fmaf(bc2[r+3], Wr1[(DIM + r+3)*DIM + j], a3);
        }
        g_bfold[j] = br1[j] + (a0 + a1) + (a2 + a3);
    }
}

// ============================================================
// Kernel 1: a = relu(ctx @ Wc1 + bc1)   (N x 256)
// ctx built on the fly: A[i, p*256+d] = wt(i,p) * E[tok[idxc(i,p)], d]
// GEMM: BM=128, BN=128, BK=32, K=1280, 256 threads (8 warps 4x2, warp 32x64)
// BN=128 halves the scattered E-gather traffic vs BN=64 (A tile reused over
// 2 column blocks instead of 4). Tiles pre-cvt to tf32; register prefetch
// double-buffer hides gather latency under the mma block.
// grid = (256, 2)
// ============================================================
#define BM1 128
#define BN1 128
#define BK  32

__global__ __launch_bounds__(256) void k_ctx(
    const int* __restrict__ tok, const float* __restrict__ E,
    const float* __restrict__ Wc1, const float* __restrict__ bc1)
{
    __shared__ unsigned As[BM1][BK+4];    // 128 x 36 (tf32 bits)
    __shared__ unsigned Bs[BK][BN1+8];    // 32 x 136 (tf32 bits, conflict-free)
    __shared__ int   eofs[CWIN][BM1];     // token*256 for each (p, row)
    __shared__ float ewt[CWIN][BM1];      // window mask weight

    const int tid = threadIdx.x;
    const int tm  = blockIdx.x;           // 0..255 (token tile)
    const int dnb = blockIdx.y * BN1;     // output-column base

    // precompute window gather offsets + masks for this row tile
    for (int t = tid; t < CWIN*BM1; t += 256) {
        int p = t >> 7;
        int r = t & (BM1-1);
        int n = tm*BM1 + r;
        int i = n & (SEQ-1);
        int b = n >> 12;
        int end   = min(SEQ, i + 3);
        int start = max(0, i - 2);
        int idx = end - CWIN + p;
        ewt[p][r] = (idx >= start) ? 1.f : 0.f;
        int idxc = min(max(idx, 0), SEQ-1);
        eofs[p][r] = tok[(b << 12) + idxc] * DIM;
    }

    const int warp = tid >> 5, lane = tid & 31;
    const int wm = warp & 3, wn = warp >> 2;
    const int lr = lane >> 2, lc = lane & 3;

    float acc[2][8][4];
    #pragma unroll
    for (int mi = 0; mi < 2; ++mi)
        #pragma unroll
        for (int ni = 0; ni < 8; ++ni)
            #pragma unroll
            for (int q = 0; q < 4; ++q) acc[mi][ni][q] = 0.f;

    __syncthreads();   // eofs/ewt ready

    uint4 aR[4], bR[4];

    // prefetch: load + mask-scale + cvt tile k0 into registers
    auto pf = [&](int k0) {
        const int p  = k0 >> 8;
        const int kp = k0 & 255;
        #pragma unroll
        for (int it = 0; it < 4; ++it) {
            int f4 = tid + it*256;
            int r  = f4 >> 3;
            int cg = (f4 & 7) << 2;
            float4 v = *(const float4*)(E + eofs[p][r] + kp + cg);
            float  w = ewt[p][r];
            aR[it].x = f2tf(v.x*w); aR[it].y = f2tf(v.y*w);
            aR[it].z = f2tf(v.z*w); aR[it].w = f2tf(v.w*w);
        }
        #pragma unroll
        for (int it = 0; it < 4; ++it) {
            int f4 = tid + it*256;
            int kr = f4 >> 5;
            int jc = (f4 & 31) << 2;
            float4 v = *(const float4*)(Wc1 + (k0 + kr)*DIM + dnb + jc);
            bR[it].x = f2tf(v.x); bR[it].y = f2tf(v.y);
            bR[it].z = f2tf(v.z); bR[it].w = f2tf(v.w);
        }
    };

    pf(0);

    for (int k0 = 0; k0 < KC; k0 += BK) {
        // commit prefetched tile to SMEM
        #pragma unroll
        for (int it = 0; it < 4; ++it) {
            int f4 = tid + it*256;
            int r  = f4 >> 3;
            int cg = (f4 & 7) << 2;
            *(uint4*)&As[r][cg] = aR[it];
        }
        #pragma unroll
        for (int it = 0; it < 4; ++it) {
            int f4 = tid + it*256;
            int kr = f4 >> 5;
            int jc = (f4 & 31) << 2;
            *(uint4*)&Bs[kr][jc] = bR[it];
        }
        __syncthreads();

        // kick off next tile's global loads (latency hidden under mma)
        if (k0 + BK < KC) pf(k0 + BK);

        #pragma unroll
        for (int kk = 0; kk < BK; kk += 8) {
            unsigned afr[2][4], bfr[8][2];
            #pragma unroll
            for (int mi = 0; mi < 2; ++mi) {
                int r = wm*32 + mi*16 + lr;
                afr[mi][0] = As[r  ][kk+lc  ];
                afr[mi][1] = As[r+8][kk+lc  ];
                afr[mi][2] = As[r  ][kk+lc+4];
                afr[mi][3] = As[r+8][kk+lc+4];
            }
            #pragma unroll
            for (int ni = 0; ni < 8; ++ni) {
                int cI = wn*64 + ni*8 + lr;
                bfr[ni][0] = Bs[kk+lc  ][cI];
                bfr[ni][1] = Bs[kk+lc+4][cI];
            }
            #pragma unroll
            for (int mi = 0; mi < 2; ++mi)
                #pragma unroll
                for (int ni = 0; ni < 8; ++ni)
                    mma8(acc[mi][ni], afr[mi], bfr[ni]);
        }
        __syncthreads();
    }

    // epilogue: relu(acc + bc1) -> g_a
    #pragma unroll
    for (int mi = 0; mi < 2; ++mi) {
        int r0 = tm*BM1 + wm*32 + mi*16 + lr;
        #pragma unroll
        for (int ni = 0; ni < 8; ++ni) {
            int col = dnb + wn*64 + ni*8 + 2*lc;
            float b0 = bc1[col], b1 = bc1[col+1];
            float2 v0, v1;
            v0.x = fmaxf(acc[mi][ni][0] + b0, 0.f);
            v0.y = fmaxf(acc[mi][ni][1] + b1, 0.f);
            v1.x = fmaxf(acc[mi][ni][2] + b0, 0.f);
            v1.y = fmaxf(acc[mi][ni][3] + b1, 0.f);
            *(float2*)&g_a[(size_t)r0*DIM + col]     = v0;
            *(float2*)&g_a[(size_t)(r0+8)*DIM + col] = v1;
        }
    }
}

// ============================================================
// Kernel 2 (fused): t = [a | static] @ [Wfold ; Wr1a]  (K=512)
//                   u = tanh(t + bfold)  (kept in SMEM as tf32)
//                   out = u @ Wr2 + br2  (K=256)
// BM=64, BN=256, 256 threads (8 warps, 2x4), warp tile 32x64
// Register prefetch double-buffer on both phases; phase-2's first B tile is
// prefetched BEFORE the tanh epilogue so the load hides under MUFU work.
// grid = 512
// ============================================================
#define BM2 64
#define BS2S 264
#define US2S 260
#define SM_AS 0
#define SM_BS (64*36)                          // 2304
#define SM_US (SM_BS + 32*BS2S)                // 10752
#define SM_TK (SM_US + 64*US2S)                // 27392
#define SM2_BYTES ((SM_TK + 64) * 4)           // 109,824 bytes

__global__ __launch_bounds__(256) void k_out(
    const int* __restrict__ tok, const float* __restrict__ E,
    const float* __restrict__ Wr1, const float* __restrict__ Wr2,
    const float* __restrict__ br2, float* __restrict__ out)
{
    extern __shared__ unsigned smu[];
    unsigned* As = smu + SM_AS;            // stride 36  (tf32 bits)
    unsigned* Bs = smu + SM_BS;            // stride 264 (tf32 bits)
    unsigned* Us = smu + SM_US;            // stride 260 (tf32 bits)
    int*      st = (int*)(smu + SM_TK);

    const int tid = threadIdx.x;
    const int tm  = blockIdx.x;            // 0..511

    for (int r = tid; r < BM2; r += 256)
        st[r] = tok[tm*BM2 + r] * DIM;

    const int warp = tid >> 5, lane = tid & 31;
    const int wm = warp & 1, wn = warp >> 1;
    const int lr = lane >> 2, lc = lane & 3;

    float acc[2][8][4];
    #pragma unroll
    for (int mi = 0; mi < 2; ++mi)
        #pragma unroll
        for (int ni = 0; ni < 8; ++ni)
            #pragma unroll
            for (int q = 0; q < 4; ++q) acc[mi][ni][q] = 0.f;

    __syncthreads();   // st[] ready

    uint4 aR[2], bR[8];

    auto pfA = [&](int k0) {
        #pragma unroll
        for (int it = 0; it < 2; ++it) {
            int f4 = tid + it*256;
            int r  = f4 >> 3;
            int cg = (f4 & 7) << 2;
            float4 v;
            if (k0 < DIM)
                v = *(const float4*)(g_a + (size_t)(tm*BM2 + r)*DIM + k0 + cg);
            else
                v = *(const float4*)(E + st[r] + (k0 - DIM) + cg);
            aR[it].x = f2tf(v.x); aR[it].y = f2tf(v.y);
            aR[it].z = f2tf(v.z); aR[it].w = f2tf(v.w);
        }
    };
    auto pfB1 = [&](int k0) {
        const float* bsrc = (k0 < DIM) ? (g_Wfold + (size_t)k0*DIM)
                                       : (Wr1 + (size_t)(k0 - DIM)*DIM);
        #pragma unroll
        for (int it = 0; it < 8; ++it) {
            int f4 = tid + it*256;
            int kr = f4 >> 6;
            int jc = (f4 & 63) << 2;
            float4 v = *(const float4*)(bsrc + (size_t)kr*DIM + jc);
            bR[it].x = f2tf(v.x); bR[it].y = f2tf(v.y);
            bR[it].z = f2tf(v.z); bR[it].w = f2tf(v.w);
        }
    };
    auto pfB2 = [&](int k0) {
        #pragma unroll
        for (int it = 0; it < 8; ++it) {
            int f4 = tid + it*256;
            int kr = f4 >> 6;
            int jc = (f4 & 63) << 2;
            float4 v = *(const float4*)(Wr2 + (size_t)(k0 + kr)*DIM + jc);
            bR[it].x = f2tf(v.x); bR[it].y = f2tf(v.y);
            bR[it].z = f2tf(v.z); bR[it].w = f2tf(v.w);
        }
    };
    auto commit = [&]() {
        #pragma unroll
        for (int it = 0; it < 2; ++it) {
            int f4 = tid + it*256;
            int r  = f4 >> 3;
            int cg = (f4 & 7) << 2;
            *(uint4*)&As[r*36 + cg] = aR[it];
        }
        #pragma unroll
        for (int it = 0; it < 8; ++it) {
            int f4 = tid + it*256;
            int kr = f4 >> 6;
            int jc = (f4 & 63) << 2;
            *(uint4*)&Bs[kr*BS2S + jc] = bR[it];
        }
    };
    auto commitB = [&]() {
        #pragma unroll
        for (int it = 0; it < 8; ++it) {
            int f4 = tid + it*256;
            int kr = f4 >> 6;
            int jc = (f4 & 63) << 2;
            *(uint4*)&Bs[kr*BS2S + jc] = bR[it];
        }
    };

    // ---- phase 1: t = [a | static] @ [Wfold ; Wr1[0:256]] , K = 512 ----
    pfA(0); pfB1(0);
    for (int k0 = 0; k0 < 2*DIM; k0 += BK) {
        commit();
        __syncthreads();
        if (k0 + BK < 2*DIM) { pfA(k0 + BK); pfB1(k0 + BK); }

        #pragma unroll
        for (int kk = 0; kk < BK; kk += 8) {
            unsigned afr[2][4], bfr[8][2];
            #pragma unroll
            for (int mi = 0; mi < 2; ++mi) {
                int r = wm*32 + mi*16 + lr;
                afr[mi][0] = As[ r   *36 + kk+lc  ];
                afr[mi][1] = As[(r+8)*36 + kk+lc  ];
                afr[mi][2] = As[ r   *36 + kk+lc+4];
                afr[mi][3] = As[(r+8)*36 + kk+lc+4];
            }
            #pragma unroll
            for (int ni = 0; ni < 8; ++ni) {
                int cI = wn*64 + ni*8 + lr;
                bfr[ni][0] = Bs[(kk+lc  )*BS2S + cI];
                bfr[ni][1] = Bs[(kk+lc+4)*BS2S + cI];
            }
            #pragma unroll
            for (int mi = 0; mi < 2; ++mi)
                #pragma unroll
                for (int ni = 0; ni < 8; ++ni)
                    mma8(acc[mi][ni], afr[mi], bfr[ni]);
        }
        __syncthreads();
    }

    // prefetch phase-2's first B tile NOW; latency hides under tanh epilogue
    pfB2(0);

    // ---- tanh epilogue -> Us (tf32); reset accumulators ----
    #pragma unroll
    for (int mi = 0; mi < 2; ++mi) {
        int r = wm*32 + mi*16 + lr;
        #pragma unroll
        for (int ni = 0; ni < 8; ++ni) {
            int col = wn*64 + ni*8 + 2*lc;
            float b0 = g_bfold[col], b1 = g_bfold[col+1];
            Us[ r   *US2S + col  ] = f2tf(tanhf(acc[mi][ni][0] + b0));
            Us[ r   *US2S + col+1] = f2tf(tanhf(acc[mi][ni][1] + b1));
            Us[(r+8)*US2S + col  ] = f2tf(tanhf(acc[mi][ni][2] + b0));
            Us[(r+8)*US2S + col+1] = f2tf(tanhf(acc[mi][ni][3] + b1));
            acc[mi][ni][0] = 0.f; acc[mi][ni][1] = 0.f;
            acc[mi][ni][2] = 0.f; acc[mi][ni][3] = 0.f;
        }
    }
    __syncthreads();

    // ---- phase 2: out = Us @ Wr2 + br2 , K = 256 ----
    for (int k0 = 0; k0 < DIM; k0 += BK) {
        commitB();
        __syncthreads();
        if (k0 + BK < DIM) pfB2(k0 + BK);

        #pragma unroll
        for (int kk = 0; kk < BK; kk += 8) {
            int kg = k0 + kk;
            unsigned afr[2][4], bfr[8][2];
            #pragma unroll
            for (int mi = 0; mi < 2; ++mi) {
                int r = wm*32 + mi*16 + lr;
                afr[mi][0] = Us[ r   *US2S + kg+lc  ];
                afr[mi][1] = Us[(r+8)*US2S + kg+lc  ];
                afr[mi][2] = Us[ r   *US2S + kg+lc+4];
                afr[mi][3] = Us[(r+8)*US2S + kg+lc+4];
            }
            #pragma unroll
            for (int ni = 0; ni < 8; ++ni) {
                int cI = wn*64 + ni*8 + lr;
                bfr[ni][0] = Bs[(kk+lc  )*BS2S + cI];
                bfr[ni][1] = Bs[(kk+lc+4)*BS2S + cI];
            }
            #pragma unroll
            for (int mi = 0; mi < 2; ++mi)
                #pragma unroll
                for (int ni = 0; ni < 8; ++ni)
                    mma8(acc[mi][ni], afr[mi], bfr[ni]);
        }
        __syncthreads();
    }

    // ---- final epilogue: + br2 -> d_out ----
    #pragma unroll
    for (int mi = 0; mi < 2; ++mi) {
        int gr = tm*BM2 + wm*32 + mi*16 + lr;
        #pragma unroll
        for (int ni = 0; ni < 8; ++ni) {
            int col = wn*64 + ni*8 + 2*lc;
            float b0 = br2[col], b1 = br2[col+1];
            float2 v;
            v.x = acc[mi][ni][0] + b0; v.y = acc[mi][ni][1] + b1;
            *(float2*)&out[(size_t)gr*DIM + col] = v;
            v.x = acc[mi][ni][2] + b0; v.y = acc[mi][ni][3] + b1;
            *(float2*)&out[(size_t)(gr+8)*DIM + col] = v;
        }
    }
}

// ============================================================
extern "C" void kernel_launch(void* const* d_in, const int* in_sizes, int n_in,
                              void* d_out, int out_size)
{
    const int*   tok = (const int*)  d_in[0];
    const float* E   = (const float*)d_in[1];
    const float* Wc1 = (const float*)d_in[2];
    const float* bc1 = (const float*)d_in[3];
    const float* Wc2 = (const float*)d_in[4];
    const float* bc2 = (const float*)d_in[5];
    const float* Wr1 = (const float*)d_in[6];
    const float* br1 = (const float*)d_in[7];
    const float* Wr2 = (const float*)d_in[8];
    const float* br2 = (const float*)d_in[9];
    float* out = (float*)d_out;

    // idempotent attribute set — safe under graph capture
    cudaFuncSetAttribute(k_out, cudaFuncAttributeMaxDynamicSharedMemorySize, SM2_BYTES);

    k_fold<<<DIM + 1, DIM>>>(Wc2, bc2, Wr1, br1);
    k_ctx<<<dim3(NTOK/BM1, DIM/BN1), 256>>>(tok, E, Wc1, bc1);
    k_out<<<NTOK/BM2, 256, SM2_BYTES>>>(tok, E, Wr1, Wr2, br2, out);
}

// round 12
// speedup vs baseline: 1.3233x; 1.3233x over previous
#include <cuda_runtime.h>

#define BATCH 8
#define SEQ   4096
#define NTOK  (BATCH*SEQ)     // 32768
#define DIM   256
#define CWIN  5
#define KC    (CWIN*DIM)      // 1280
#define BK    32

// ---- device scratch (static globals: allowed; no runtime allocation) ----
__device__ float g_a[(size_t)NTOK * DIM];   // relu(ctx@Wc1 + bc1), 33.5 MB
__device__ float g_Wfold[DIM * DIM];        // Wc2 @ Wr1[256:512]
__device__ float g_bfold[DIM];              // bc2 @ Wr1[256:512] + br1

// ---- tf32 helpers ----
__device__ __forceinline__ unsigned f2tf(float f) {
    unsigned u;
    asm("cvt.rna.tf32.f32 %0, %1;" : "=r"(u) : "f"(f));
    return u;
}

__device__ __forceinline__ void mma8(float* c, const unsigned* a, const unsigned* b) {
    asm volatile(
        "mma.sync.aligned.m16n8k8.row.col.f32.tf32.tf32.f32 "
        "{%0,%1,%2,%3}, {%4,%5,%6,%7}, {%8,%9}, {%0,%1,%2,%3};\n"
        : "+f"(c[0]), "+f"(c[1]), "+f"(c[2]), "+f"(c[3])
        : "r"(a[0]), "r"(a[1]), "r"(a[2]), "r"(a[3]), "r"(b[0]), "r"(b[1]));
}

// ============================================================
// Kernel 0: fold Wc2 into Wr1's h-half.
//   Wfold[k,j] = sum_r Wc2[k,r]*Wr1[256+r, j]
// k_fold is LOAD-LATENCY bound (measured: 20.7us, issue 9.4%), not chain
// bound. Fix = MLP: 8 accumulators x unroll 4 -> 32 independent loads in
// flight per thread.
// grid = 257 blocks x 256 threads (block 256 does the bias)
// ============================================================
__global__ void k_fold(const float* __restrict__ Wc2, const float* __restrict__ bc2,
                       const float* __restrict__ Wr1, const float* __restrict__ br1)
{
    int j = threadIdx.x;
    int k = blockIdx.x;
    const float* __restrict__ wrow = (k < DIM) ? (Wc2 + k*DIM) : bc2;
    float a[8];
    #pragma unroll
    for (int u = 0; u < 8; ++u) a[u] = 0.f;
    #pragma unroll 4
    for (int r = 0; r < DIM; r += 8) {
        #pragma unroll
        for (int u = 0; u < 8; ++u)
            a[u] = fmaf(wrow[r+u], Wr1[(DIM + r + u)*DIM + j], a[u]);
    }
    float s = ((a[0]+a[1]) + (a[2]+a[3])) + ((a[4]+a[5]) + (a[6]+a[7]));
    if (k < DIM) g_Wfold[k*DIM + j] = s;
    else         g_bfold[j] = br1[j] + s;
}

// ============================================================
// Kernel 1: a = relu(ctx @ Wc1 + bc1)   (N x 256)
// Halo-dedup, FULL-WIDTH staging: the 70 distinct halo rows (seq positions
// [ts-4, ts+65]) are the SAME for all 5 window slots p, so stage the entire
// 70x256 halo (pre-cvt tf32) in SMEM ONCE per block -- not per k-tile.
// mma A-fragments read through a per-(p,row) index map at column (k0&255);
// masked slots map to zero row 70. k-loop only streams the L2-resident Wc1
// tile. Per-block E-gather: 358 KB (R4 design) -> 72 KB.
// BM=64, BN=256, 256 threads (8 warps 2x4, warp 32x64), occ 2 (smem-limited).
// grid = 512
// ============================================================
#define BM1 64
#define ECH_S 260                       // halo stride: banks (row*4+lc)%32 all unique
#define BS1S  264                       // Bs stride (conflict-free fragment reads)
#define SM1_BYTES ((71*ECH_S + 32*BS1S + CWIN*BM1) * 4)   // 108,912 B

__global__ __launch_bounds__(256, 2) void k_ctx(
    const int* __restrict__ tok, const float* __restrict__ E,
    const float* __restrict__ Wc1, const float* __restrict__ bc1)
{
    extern __shared__ unsigned sm1[];
    unsigned* Ech = sm1;                         // 71 x 260 (70 halo rows + zero)
    unsigned* Bs  = sm1 + 71*ECH_S;              // 32 x 264
    int*     rmap = (int*)(sm1 + 71*ECH_S + 32*BS1S);  // (p,r) -> halo row
    __shared__ int heofs[70];                    // E offset per halo row

    const int tid = threadIdx.x;
    const int tm  = blockIdx.x;            // 0..511 (64-token tile)
    const int ts  = (tm * BM1) & (SEQ-1);  // seq start of tile
    const int b   = (tm * BM1) >> 12;      // batch index
    const int hstart = max(0, ts - 4);
    const int hend   = min(SEQ - 1, ts + 65);

    // one-time per block: halo E offsets, slot->halo map, zero row
    if (tid < 70)
        heofs[tid] = tok[(b << 12) + min(hstart + tid, hend)] << 8;  // *DIM
    for (int t = tid; t < CWIN*BM1; t += 256) {
        int p = t >> 6;
        int r = t & (BM1-1);
        int i = ts + r;
        int end   = min(SEQ, i + 3);
        int start = max(0, i - 2);
        int idx = end - CWIN + p;
        rmap[t] = (idx >= start) ? (max(idx, 0) - hstart) : 70;
    }
    Ech[70*ECH_S + tid] = 0;               // zero row cols 0..255 (never overwritten)
    __syncthreads();                       // heofs ready for staging

    // stage the full 70x256 halo once (4480 float4, 17.5 per thread, MLP-rich)
    for (int c = tid; c < 70*64; c += 256) {
        int q = c >> 6, f = (c & 63) << 2;
        float4 v = *(const float4*)(E + heofs[q] + f);
        uint4 u; u.x = f2tf(v.x); u.y = f2tf(v.y); u.z = f2tf(v.z); u.w = f2tf(v.w);
        *(uint4*)&Ech[q*ECH_S + f] = u;
    }
    // (first k-tile's __syncthreads below also fences the halo staging)

    const int warp = tid >> 5, lane = tid & 31;
    const int wm = warp & 1, wn = warp >> 1;
    const int lr = lane >> 2, lc = lane & 3;

    float acc[2][8][4];
    #pragma unroll
    for (int mi = 0; mi < 2; ++mi)
        #pragma unroll
        for (int ni = 0; ni < 8; ++ni)
            #pragma unroll
            for (int q = 0; q < 4; ++q) acc[mi][ni][q] = 0.f;

    for (int k0 = 0; k0 < KC; k0 += BK) {
        // Wc1 tile 32x256 (L2-resident): direct load + cvt + store
        #pragma unroll
        for (int it = 0; it < 8; ++it) {
            int c2 = tid + it*256;
            int kr = c2 >> 6, jc = (c2 & 63) << 2;
            float4 v = *(const float4*)(Wc1 + (size_t)(k0 + kr)*DIM + jc);
            uint4 u; u.x = f2tf(v.x); u.y = f2tf(v.y); u.z = f2tf(v.z); u.w = f2tf(v.w);
            *(uint4*)&Bs[kr*BS1S + jc] = u;
        }
        __syncthreads();

        const int p  = k0 >> 8;
        const int kp = k0 & 255;
        int rm[2][2];
        rm[0][0] = rmap[p*BM1 + wm*32 + lr];
        rm[0][1] = rmap[p*BM1 + wm*32 + lr + 8];
        rm[1][0] = rmap[p*BM1 + wm*32 + 16 + lr];
        rm[1][1] = rmap[p*BM1 + wm*32 + 24 + lr];

        #pragma unroll
        for (int kk = 0; kk < BK; kk += 8) {
            unsigned afr[2][4], bfr[8][2];
            #pragma unroll
            for (int mi = 0; mi < 2; ++mi) {
                afr[mi][0] = Ech[rm[mi][0]*ECH_S + kp+kk+lc  ];
                afr[mi][1] = Ech[rm[mi][1]*ECH_S + kp+kk+lc  ];
                afr[mi][2] = Ech[rm[mi][0]*ECH_S + kp+kk+lc+4];
                afr[mi][3] = Ech[rm[mi][1]*ECH_S + kp+kk+lc+4];
            }
            #pragma unroll
            for (int ni = 0; ni < 8; ++ni) {
                int cI = wn*64 + ni*8 + lr;
                bfr[ni][0] = Bs[(kk+lc  )*BS1S + cI];
                bfr[ni][1] = Bs[(kk+lc+4)*BS1S + cI];
            }
            #pragma unroll
            for (int mi = 0; mi < 2; ++mi)
                #pragma unroll
                for (int ni = 0; ni < 8; ++ni)
                    mma8(acc[mi][ni], afr[mi], bfr[ni]);
        }
        __syncthreads();
    }

    // epilogue: relu(acc + bc1) -> g_a
    #pragma unroll
    for (int mi = 0; mi < 2; ++mi) {
        int r0 = tm*BM1 + wm*32 + mi*16 + lr;
        #pragma unroll
        for (int ni = 0; ni < 8; ++ni) {
            int col = wn*64 + ni*8 + 2*lc;
            float b0 = bc1[col], b1 = bc1[col+1];
            float2 v0, v1;
            v0.x = fmaxf(acc[mi][ni][0] + b0, 0.f);
            v0.y = fmaxf(acc[mi][ni][1] + b1, 0.f);
            v1.x = fmaxf(acc[mi][ni][2] + b0, 0.f);
            v1.y = fmaxf(acc[mi][ni][3] + b1, 0.f);
            *(float2*)&g_a[(size_t)r0*DIM + col]     = v0;
            *(float2*)&g_a[(size_t)(r0+8)*DIM + col] = v1;
        }
    }
}

// ============================================================
// Kernel 2 (fused): t = [a | static] @ [Wfold ; Wr1a]  (K=512)
//                   u = tanh(t + bfold)  (kept in SMEM as tf32)
//                   out = u @ Wr2 + br2  (K=256)
// BM=64, BN=256, 256 threads (8 warps, 2x4), warp tile 32x64
// (R2-measured version: no register prefetch -- protects occupancy 2)
// grid = 512
// ============================================================
#define BM2 64
#define BS2S 264
#define US2S 260
#define SM_AS 0
#define SM_BS (64*36)                          // 2304
#define SM_US (SM_BS + 32*BS2S)                // 10752
#define SM_TK (SM_US + 64*US2S)                // 27392
#define SM2_BYTES ((SM_TK + 64) * 4)           // 109,824 bytes

__global__ __launch_bounds__(256) void k_out(
    const int* __restrict__ tok, const float* __restrict__ E,
    const float* __restrict__ Wr1, const float* __restrict__ Wr2,
    const float* __restrict__ br2, float* __restrict__ out)
{
    extern __shared__ unsigned smu[];
    unsigned* As = smu + SM_AS;            // stride 36  (tf32 bits)
    unsigned* Bs = smu + SM_BS;            // stride 264 (tf32 bits)
    unsigned* Us = smu + SM_US;            // stride 260 (tf32 bits)
    int*      st = (int*)(smu + SM_TK);

    const int tid = threadIdx.x;
    const int tm  = blockIdx.x;            // 0..511

    for (int r = tid; r < BM2; r += 256)
        st[r] = tok[tm*BM2 + r] * DIM;

    const int warp = tid >> 5, lane = tid & 31;
    const int wm = warp & 1, wn = warp >> 1;
    const int lr = lane >> 2, lc = lane & 3;

    float acc[2][8][4];
    #pragma unroll
    for (int mi = 0; mi < 2; ++mi)
        #pragma unroll
        for (int ni = 0; ni < 8; ++ni)
            #pragma unroll
            for (int q = 0; q < 4; ++q) acc[mi][ni][q] = 0.f;

    __syncthreads();

    // ---- phase 1: t = [a | static] @ [Wfold ; Wr1[0:256]] , K = 512 ----
    for (int k0 = 0; k0 < 2*DIM; k0 += BK) {
        // A tile 64x32 -> 512 float4, 2 per thread (pre-cvt to tf32)
        #pragma unroll
        for (int it = 0; it < 2; ++it) {
            int f4 = tid + it*256;
            int r  = f4 >> 3;
            int cg = (f4 & 7) << 2;
            float4 v;
            if (k0 < DIM)
                v = *(const float4*)(g_a + (size_t)(tm*BM2 + r)*DIM + k0 + cg);
            else
                v = *(const float4*)(E + st[r] + (k0 - DIM) + cg);
            uint4 u; u.x = f2tf(v.x); u.y = f2tf(v.y); u.z = f2tf(v.z); u.w = f2tf(v.w);
            *(uint4*)&As[r*36 + cg] = u;
        }
        // B tile 32x256 -> 2048 float4, 8 per thread (pre-cvt to tf32)
        const float* bsrc = (k0 < DIM) ? (g_Wfold + (size_t)k0*DIM)
                                       : (Wr1 + (size_t)(k0 - DIM)*DIM);
        #pragma unroll
        for (int it = 0; it < 8; ++it) {
            int f4 = tid + it*256;
            int kr = f4 >> 6;
            int jc = (f4 & 63) << 2;
            float4 v = *(const float4*)(bsrc + (size_t)kr*DIM + jc);
            uint4 u; u.x = f2tf(v.x); u.y = f2tf(v.y); u.z = f2tf(v.z); u.w = f2tf(v.w);
            *(uint4*)&Bs[kr*BS2S + jc] = u;
        }
        __syncthreads();

        #pragma unroll
        for (int kk = 0; kk < BK; kk += 8) {
            unsigned afr[2][4], bfr[8][2];
            #pragma unroll
            for (int mi = 0; mi < 2; ++mi) {
                int r = wm*32 + mi*16 + lr;
                afr[mi][0] = As[ r   *36 + kk+lc  ];
                afr[mi][1] = As[(r+8)*36 + kk+lc  ];
                afr[mi][2] = As[ r   *36 + kk+lc+4];
                afr[mi][3] = As[(r+8)*36 + kk+lc+4];
            }
            #pragma unroll
            for (int ni = 0; ni < 8; ++ni) {
                int cI = wn*64 + ni*8 + lr;
                bfr[ni][0] = Bs[(kk+lc  )*BS2S + cI];
                bfr[ni][1] = Bs[(kk+lc+4)*BS2S + cI];
            }
            #pragma unroll
            for (int mi = 0; mi < 2; ++mi)
                #pragma unroll
                for (int ni = 0; ni < 8; ++ni)
                    mma8(acc[mi][ni], afr[mi], bfr[ni]);
        }
        __syncthreads();
    }

    // ---- tanh epilogue -> Us (tf32); reset accumulators ----
    #pragma unroll
    for (int mi = 0; mi < 2; ++mi) {
        int r = wm*32 + mi*16 + lr;
        #pragma unroll
        for (int ni = 0; ni < 8; ++ni) {
            int col = wn*64 + ni*8 + 2*lc;
            float b0 = g_bfold[col], b1 = g_bfold[col+1];
            Us[ r   *US2S + col  ] = f2tf(tanhf(acc[mi][ni][0] + b0));
            Us[ r   *US2S + col+1] = f2tf(tanhf(acc[mi][ni][1] + b1));
            Us[(r+8)*US2S + col  ] = f2tf(tanhf(acc[mi][ni][2] + b0));
            Us[(r+8)*US2S + col+1] = f2tf(tanhf(acc[mi][ni][3] + b1));
            acc[mi][ni][0] = 0.f; acc[mi][ni][1] = 0.f;
            acc[mi][ni][2] = 0.f; acc[mi][ni][3] = 0.f;
        }
    }
    __syncthreads();

    // ---- phase 2: out = Us @ Wr2 + br2 , K = 256 ----
    for (int k0 = 0; k0 < DIM; k0 += BK) {
        #pragma unroll
        for (int it = 0; it < 8; ++it) {
            int f4 = tid + it*256;
            int kr = f4 >> 6;
            int jc = (f4 & 63) << 2;
            float4 v = *(const float4*)(Wr2 + (size_t)(k0 + kr)*DIM + jc);
            uint4 u; u.x = f2tf(v.x); u.y = f2tf(v.y); u.z = f2tf(v.z); u.w = f2tf(v.w);
            *(uint4*)&Bs[kr*BS2S + jc] = u;
        }
        __syncthreads();

        #pragma unroll
        for (int kk = 0; kk < BK; kk += 8) {
            int kg = k0 + kk;
            unsigned afr[2][4], bfr[8][2];
            #pragma unroll
            for (int mi = 0; mi < 2; ++mi) {
                int r = wm*32 + mi*16 + lr;
                afr[mi][0] = Us[ r   *US2S + kg+lc  ];
                afr[mi][1] = Us[(r+8)*US2S + kg+lc  ];
                afr[mi][2] = Us[ r   *US2S + kg+lc+4];
                afr[mi][3] = Us[(r+8)*US2S + kg+lc+4];
            }
            #pragma unroll
            for (int ni = 0; ni < 8; ++ni) {
                int cI = wn*64 + ni*8 + lr;
                bfr[ni][0] = Bs[(kk+lc  )*BS2S + cI];
                bfr[ni][1] = Bs[(kk+lc+4)*BS2S + cI];
            }
            #pragma unroll
            for (int mi = 0; mi < 2; ++mi)
                #pragma unroll
                for (int ni = 0; ni < 8; ++ni)
                    mma8(acc[mi][ni], afr[mi], bfr[ni]);
        }
        __syncthreads();
    }

    // ---- final epilogue: + br2 -> d_out ----
    #pragma unroll
    for (int mi = 0; mi < 2; ++mi) {
        int gr = tm*BM2 + wm*32 + mi*16 + lr;
        #pragma unroll
        for (int ni = 0; ni < 8; ++ni) {
            int col = wn*64 + ni*8 + 2*lc;
            float b0 = br2[col], b1 = br2[col+1];
            float2 v;
            v.x = acc[mi][ni][0] + b0; v.y = acc[mi][ni][1] + b1;
            *(float2*)&out[(size_t)gr*DIM + col] = v;
            v.x = acc[mi][ni][2] + b0; v.y = acc[mi][ni][3] + b1;
            *(float2*)&out[(size_t)(gr+8)*DIM + col] = v;
        }
    }
}

// ============================================================
extern "C" void kernel_launch(void* const* d_in, const int* in_sizes, int n_in,
                              void* d_out, int out_size)
{
    const int*   tok = (const int*)  d_in[0];
    const float* E   = (const float*)d_in[1];
    const float* Wc1 = (const float*)d_in[2];
    const float* bc1 = (const float*)d_in[3];
    const float* Wc2 = (const float*)d_in[4];
    const float* bc2 = (const float*)d_in[5];
    const float* Wr1 = (const float*)d_in[6];
    const float* br1 = (const float*)d_in[7];
    const float* Wr2 = (const float*)d_in[8];
    const float* br2 = (const float*)d_in[9];
    float* out = (float*)d_out;

    // idempotent attribute sets — safe under graph capture
    cudaFuncSetAttribute(k_ctx, cudaFuncAttributeMaxDynamicSharedMemorySize, SM1_BYTES);
    cudaFuncSetAttribute(k_out, cudaFuncAttributeMaxDynamicSharedMemorySize, SM2_BYTES);

    k_fold<<<DIM + 1, DIM>>>(Wc2, bc2, Wr1, br1);
    k_ctx<<<NTOK/BM1, 256, SM1_BYTES>>>(tok, E, Wc1, bc1);
    k_out<<<NTOK/BM2, 256, SM2_BYTES>>>(tok, E, Wr1, Wr2, br2, out);
}

// round 13
// speedup vs baseline: 1.3304x; 1.0054x over previous
#include <cuda_runtime.h>

#define BATCH 8
#define SEQ   4096
#define NTOK  (BATCH*SEQ)     // 32768
#define DIM   256
#define CWIN  5
#define KC    (CWIN*DIM)      // 1280
#define BK    32

// ---- device scratch (static globals: allowed; no runtime allocation) ----
__device__ unsigned g_at[(size_t)NTOK * DIM];  // relu(ctx@Wc1+bc1) as tf32 bits
__device__ unsigned g_Wfoldt[DIM * DIM];       // (Wc2 @ Wr1[256:512]) as tf32 bits
__device__ float    g_bfold[DIM];              // bc2 @ Wr1[256:512] + br1
__device__ unsigned g_Wc1t[KC * DIM];          // Wc1 as tf32 bits (1.31 MB)
__device__ unsigned g_Wr1t[DIM * DIM];         // Wr1 rows 0..255 as tf32 bits
__device__ unsigned g_Wr2t[DIM * DIM];         // Wr2 as tf32 bits

// ---- tf32 helpers ----
__device__ __forceinline__ unsigned f2tf(float f) {
    unsigned u;
    asm("cvt.rna.tf32.f32 %0, %1;" : "=r"(u) : "f"(f));
    return u;
}

__device__ __forceinline__ void mma8(float* c, const unsigned* a, const unsigned* b) {
    asm volatile(
        "mma.sync.aligned.m16n8k8.row.col.f32.tf32.tf32.f32 "
        "{%0,%1,%2,%3}, {%4,%5,%6,%7}, {%8,%9}, {%0,%1,%2,%3};\n"
        : "+f"(c[0]), "+f"(c[1]), "+f"(c[2]), "+f"(c[3])
        : "r"(a[0]), "r"(a[1]), "r"(a[2]), "r"(a[3]), "r"(b[0]), "r"(b[1]));
}

// ============================================================
// Kernel P: one-time tf32 pre-conversion of weights.
// 512 GEMM blocks currently re-convert the SAME weights every tile;
// converting once removes all cvt from the hot tile-fill loops.
// 114,688 float4 total = 448 blocks x 256 threads x 1 float4.
// ============================================================
__global__ void k_prep(const float* __restrict__ Wc1,
                       const float* __restrict__ Wr1,
                       const float* __restrict__ Wr2)
{
    int t = blockIdx.x * 256 + threadIdx.x;   // float4 index
    const float4* src;
    uint4* dst;
    int off;
    if (t < 81920)       { src = (const float4*)Wc1; dst = (uint4*)g_Wc1t; off = t; }
    else if (t < 98304)  { src = (const float4*)Wr1; dst = (uint4*)g_Wr1t; off = t - 81920; }
    else                 { src = (const float4*)Wr2; dst = (uint4*)g_Wr2t; off = t - 98304; }
    float4 v = src[off];
    uint4 u; u.x = f2tf(v.x); u.y = f2tf(v.y); u.z = f2tf(v.z); u.w = f2tf(v.w);
    dst[off] = u;
}

// ============================================================
// Kernel 0: fold Wc2 into Wr1's h-half -> g_Wfoldt (tf32 bits).
// R12 post-mortem: 8-acc x 32-load batches SERIALIZED at regs=31 (MLP_eff is
// reg-allocation-derived). New shape: 128 blocks x 2 k-rows, Wc2 rows staged
// in SMEM, thread j streams coalesced Wr1 loads with unroll 8 (8 loads in
// flight on ~16 live regs), 2 independent FMA chains. Block 128 = bias.
// ============================================================
__global__ void k_fold(const float* __restrict__ Wc2, const float* __restrict__ bc2,
                       const float* __restrict__ Wr1, const float* __restrict__ br1)
{
    __shared__ float wc2s[2 * DIM];
    const int j = threadIdx.x;
    const int blk = blockIdx.x;
    if (blk < 128) {
        const int k0 = blk * 2;
        // stage 2 Wc2 rows (512 floats, contiguous)
        wc2s[j]       = Wc2[k0*DIM + j];
        wc2s[j + 256] = Wc2[k0*DIM + 256 + j];
        __syncthreads();
        float a0 = 0.f, a1 = 0.f;
        #pragma unroll 8
        for (int r = 0; r < DIM; ++r) {
            float w = Wr1[(DIM + r)*DIM + j];
            a0 = fmaf(wc2s[r],       w, a0);
            a1 = fmaf(wc2s[DIM + r], w, a1);
        }
        g_Wfoldt[(k0    )*DIM + j] = f2tf(a0);
        g_Wfoldt[(k0 + 1)*DIM + j] = f2tf(a1);
    } else {
        float acc = br1[j];
        #pragma unroll 8
        for (int r = 0; r < DIM; ++r)
            acc = fmaf(bc2[r], Wr1[(DIM + r)*DIM + j], acc);
        g_bfold[j] = acc;
    }
}

// ============================================================
// Kernel 1: a = relu(ctx @ Wc1 + bc1)   (N x 256) -> g_at (tf32 bits)
// Halo-dedup, FULL-WIDTH staging (measured R12 as part of the 322us pass):
// 70 distinct halo rows staged in SMEM once per block; A-fragments read via
// per-(p,row) index map; masked slots -> zero row 70. Wc1 tiles now load
// PRE-CONVERTED tf32 bits (raw uint4 copy, no cvt in the hot loop).
// BM=64, BN=256, 256 threads (8 warps 2x4, warp 32x64), occ 2.
// grid = 512
// ============================================================
#define BM1 64
#define ECH_S 260                       // halo stride: banks (row*4+lc)%32 all unique
#define BS1S  264                       // Bs stride (conflict-free fragment reads)
#define SM1_BYTES ((71*ECH_S + 32*BS1S + CWIN*BM1) * 4)   // 108,912 B

__global__ __launch_bounds__(256, 2) void k_ctx(
    const int* __restrict__ tok, const float* __restrict__ E,
    const float* __restrict__ bc1)
{
    extern __shared__ unsigned sm1[];
    unsigned* Ech = sm1;                         // 71 x 260 (70 halo rows + zero)
    unsigned* Bs  = sm1 + 71*ECH_S;              // 32 x 264
    int*     rmap = (int*)(sm1 + 71*ECH_S + 32*BS1S);  // (p,r) -> halo row
    __shared__ int heofs[70];                    // E offset per halo row

    const int tid = threadIdx.x;
    const int tm  = blockIdx.x;            // 0..511 (64-token tile)
    const int ts  = (tm * BM1) & (SEQ-1);  // seq start of tile
    const int b   = (tm * BM1) >> 12;      // batch index
    const int hstart = max(0, ts - 4);
    const int hend   = min(SEQ - 1, ts + 65);

    // one-time per block: halo E offsets, slot->halo map, zero row
    if (tid < 70)
        heofs[tid] = tok[(b << 12) + min(hstart + tid, hend)] << 8;  // *DIM
    for (int t = tid; t < CWIN*BM1; t += 256) {
        int p = t >> 6;
        int r = t & (BM1-1);
        int i = ts + r;
        int end   = min(SEQ, i + 3);
        int start = max(0, i - 2);
        int idx = end - CWIN + p;
        rmap[t] = (idx >= start) ? (max(idx, 0) - hstart) : 70;
    }
    Ech[70*ECH_S + tid] = 0;               // zero row cols 0..255 (never overwritten)
    __syncthreads();                       // heofs ready for staging

    // stage the full 70x256 halo once (4480 float4, MLP-rich; E needs cvt)
    for (int c = tid; c < 70*64; c += 256) {
        int q = c >> 6, f = (c & 63) << 2;
        float4 v = *(const float4*)(E + heofs[q] + f);
        uint4 u; u.x = f2tf(v.x); u.y = f2tf(v.y); u.z = f2tf(v.z); u.w = f2tf(v.w);
        *(uint4*)&Ech[q*ECH_S + f] = u;
    }
    // (first k-tile's __syncthreads below also fences the halo staging)

    const int warp = tid >> 5, lane = tid & 31;
    const int wm = warp & 1, wn = warp >> 1;
    const int lr = lane >> 2, lc = lane & 3;

    float acc[2][8][4];
    #pragma unroll
    for (int mi = 0; mi < 2; ++mi)
        #pragma unroll
        for (int ni = 0; ni < 8; ++ni)
            #pragma unroll
            for (int q = 0; q < 4; ++q) acc[mi][ni][q] = 0.f;

    for (int k0 = 0; k0 < KC; k0 += BK) {
        // Wc1 tile 32x256: raw uint4 copy of pre-converted tf32 bits
        #pragma unroll
        for (int it = 0; it < 8; ++it) {
            int c2 = tid + it*256;
            int kr = c2 >> 6, jc = (c2 & 63) << 2;
            uint4 u = *(const uint4*)(g_Wc1t + (size_t)(k0 + kr)*DIM + jc);
            *(uint4*)&Bs[kr*BS1S + jc] = u;
        }
        __syncthreads();

        const int p  = k0 >> 8;
        const int kp = k0 & 255;
        int rm[2][2];
        rm[0][0] = rmap[p*BM1 + wm*32 + lr];
        rm[0][1] = rmap[p*BM1 + wm*32 + lr + 8];
        rm[1][0] = rmap[p*BM1 + wm*32 + 16 + lr];
        rm[1][1] = rmap[p*BM1 + wm*32 + 24 + lr];

        #pragma unroll
        for (int kk = 0; kk < BK; kk += 8) {
            unsigned afr[2][4], bfr[8][2];
            #pragma unroll
            for (int mi = 0; mi < 2; ++mi) {
                afr[mi][0] = Ech[rm[mi][0]*ECH_S + kp+kk+lc  ];
                afr[mi][1] = Ech[rm[mi][1]*ECH_S + kp+kk+lc  ];
                afr[mi][2] = Ech[rm[mi][0]*ECH_S + kp+kk+lc+4];
                afr[mi][3] = Ech[rm[mi][1]*ECH_S + kp+kk+lc+4];
            }
            #pragma unroll
            for (int ni = 0; ni < 8; ++ni) {
                int cI = wn*64 + ni*8 + lr;
                bfr[ni][0] = Bs[(kk+lc  )*BS1S + cI];
                bfr[ni][1] = Bs[(kk+lc+4)*BS1S + cI];
            }
            #pragma unroll
            for (int mi = 0; mi < 2; ++mi)
                #pragma unroll
                for (int ni = 0; ni < 8; ++ni)
                    mma8(acc[mi][ni], afr[mi], bfr[ni]);
        }
        __syncthreads();
    }

    // epilogue: relu(acc + bc1) -> g_at as tf32 bits (same rna rounding that
    // k_out would apply; moved here so k_out's A-loads are raw copies)
    #pragma unroll
    for (int mi = 0; mi < 2; ++mi) {
        int r0 = tm*BM1 + wm*32 + mi*16 + lr;
        #pragma unroll
        for (int ni = 0; ni < 8; ++ni) {
            int col = wn*64 + ni*8 + 2*lc;
            float b0 = bc1[col], b1 = bc1[col+1];
            uint2 v0, v1;
            v0.x = f2tf(fmaxf(acc[mi][ni][0] + b0, 0.f));
            v0.y = f2tf(fmaxf(acc[mi][ni][1] + b1, 0.f));
            v1.x = f2tf(fmaxf(acc[mi][ni][2] + b0, 0.f));
            v1.y = f2tf(fmaxf(acc[mi][ni][3] + b1, 0.f));
            *(uint2*)&g_at[(size_t)r0*DIM + col]     = v0;
            *(uint2*)&g_at[(size_t)(r0+8)*DIM + col] = v1;
        }
    }
}

// ============================================================
// Kernel 2 (fused): t = [a | static] @ [Wfold ; Wr1a]  (K=512)
//                   u = tanh(t + bfold)  (kept in SMEM as tf32)
//                   out = u @ Wr2 + br2  (K=256)
// BM=64, BN=256, 256 threads (8 warps, 2x4), warp tile 32x64
// B tiles + g_at A tiles now load PRE-CONVERTED tf32 bits (no cvt).
// grid = 512
// ============================================================
#define BM2 64
#define BS2S 264
#define US2S 260
#define SM_AS 0
#define SM_BS (64*36)                          // 2304
#define SM_US (SM_BS + 32*BS2S)                // 10752
#define SM_TK (SM_US + 64*US2S)                // 27392
#define SM2_BYTES ((SM_TK + 64) * 4)           // 109,824 bytes

__global__ __launch_bounds__(256) void k_out(
    const int* __restrict__ tok, const float* __restrict__ E,
    const float* __restrict__ br2, float* __restrict__ out)
{
    extern __shared__ unsigned smu[];
    unsigned* As = smu + SM_AS;            // stride 36  (tf32 bits)
    unsigned* Bs = smu + SM_BS;            // stride 264 (tf32 bits)
    unsigned* Us = smu + SM_US;            // stride 260 (tf32 bits)
    int*      st = (int*)(smu + SM_TK);

    const int tid = threadIdx.x;
    const int tm  = blockIdx.x;            // 0..511

    for (int r = tid; r < BM2; r += 256)
        st[r] = tok[tm*BM2 + r] * DIM;

    const int warp = tid >> 5, lane = tid & 31;
    const int wm = warp & 1, wn = warp >> 1;
    const int lr = lane >> 2, lc = lane & 3;

    float acc[2][8][4];
    #pragma unroll
    for (int mi = 0; mi < 2; ++mi)
        #pragma unroll
        for (int ni = 0; ni < 8; ++ni)
            #pragma unroll
            for (int q = 0; q < 4; ++q) acc[mi][ni][q] = 0.f;

    __syncthreads();

    // ---- phase 1: t = [a | static] @ [Wfold ; Wr1[0:256]] , K = 512 ----
    for (int k0 = 0; k0 < 2*DIM; k0 += BK) {
        // A tile 64x32: g_at half is raw uint4; E half needs cvt
        #pragma unroll
        for (int it = 0; it < 2; ++it) {
            int f4 = tid + it*256;
            int r  = f4 >> 3;
            int cg = (f4 & 7) << 2;
            uint4 u;
            if (k0 < DIM) {
                u = *(const uint4*)(g_at + (size_t)(tm*BM2 + r)*DIM + k0 + cg);
            } else {
                float4 v = *(const float4*)(E + st[r] + (k0 - DIM) + cg);
                u.x = f2tf(v.x); u.y = f2tf(v.y); u.z = f2tf(v.z); u.w = f2tf(v.w);
            }
            *(uint4*)&As[r*36 + cg] = u;
        }
        // B tile 32x256: raw uint4 copy of pre-converted tf32 bits
        const unsigned* bsrc = (k0 < DIM) ? (g_Wfoldt + (size_t)k0*DIM)
                                          : (g_Wr1t + (size_t)(k0 - DIM)*DIM);
        #pragma unroll
        for (int it = 0; it < 8; ++it) {
            int f4 = tid + it*256;
            int kr = f4 >> 6;
            int jc = (f4 & 63) << 2;
            *(uint4*)&Bs[kr*BS2S + jc] = *(const uint4*)(bsrc + (size_t)kr*DIM + jc);
        }
        __syncthreads();

        #pragma unroll
        for (int kk = 0; kk < BK; kk += 8) {
            unsigned afr[2][4], bfr[8][2];
            #pragma unroll
            for (int mi = 0; mi < 2; ++mi) {
                int r = wm*32 + mi*16 + lr;
                afr[mi][0] = As[ r   *36 + kk+lc  ];
                afr[mi][1] = As[(r+8)*36 + kk+lc  ];
                afr[mi][2] = As[ r   *36 + kk+lc+4];
                afr[mi][3] = As[(r+8)*36 + kk+lc+4];
            }
            #pragma unroll
            for (int ni = 0; ni < 8; ++ni) {
                int cI = wn*64 + ni*8 + lr;
                bfr[ni][0] = Bs[(kk+lc  )*BS2S + cI];
                bfr[ni][1] = Bs[(kk+lc+4)*BS2S + cI];
            }
            #pragma unroll
            for (int mi = 0; mi < 2; ++mi)
                #pragma unroll
                for (int ni = 0; ni < 8; ++ni)
                    mma8(acc[mi][ni], afr[mi], bfr[ni]);
        }
        __syncthreads();
    }

    // ---- tanh epilogue -> Us (tf32); reset accumulators ----
    #pragma unroll
    for (int mi = 0; mi < 2; ++mi) {
        int r = wm*32 + mi*16 + lr;
        #pragma unroll
        for (int ni = 0; ni < 8; ++ni) {
            int col = wn*64 + ni*8 + 2*lc;
            float b0 = g_bfold[col], b1 = g_bfold[col+1];
            Us[ r   *US2S + col  ] = f2tf(tanhf(acc[mi][ni][0] + b0));
            Us[ r   *US2S + col+1] = f2tf(tanhf(acc[mi][ni][1] + b1));
            Us[(r+8)*US2S + col  ] = f2tf(tanhf(acc[mi][ni][2] + b0));
            Us[(r+8)*US2S + col+1] = f2tf(tanhf(acc[mi][ni][3] + b1));
            acc[mi][ni][0] = 0.f; acc[mi][ni][1] = 0.f;
            acc[mi][ni][2] = 0.f; acc[mi][ni][3] = 0.f;
        }
    }
    __syncthreads();

    // ---- phase 2: out = Us @ Wr2 + br2 , K = 256 ----
    for (int k0 = 0; k0 < DIM; k0 += BK) {
        #pragma unroll
        for (int it = 0; it < 8; ++it) {
            int f4 = tid + it*256;
            int kr = f4 >> 6;
            int jc = (f4 & 63) << 2;
            *(uint4*)&Bs[kr*BS2S + jc] =
                *(const uint4*)(g_Wr2t + (size_t)(k0 + kr)*DIM + jc);
        }
        __syncthreads();

        #pragma unroll
        for (int kk = 0; kk < BK; kk += 8) {
            int kg = k0 + kk;
            unsigned afr[2][4], bfr[8][2];
            #pragma unroll
            for (int mi = 0; mi < 2; ++mi) {
                int r = wm*32 + mi*16 + lr;
                afr[mi][0] = Us[ r   *US2S + kg+lc  ];
                afr[mi][1] = Us[(r+8)*US2S + kg+lc  ];
                afr[mi][2] = Us[ r   *US2S + kg+lc+4];
                afr[mi][3] = Us[(r+8)*US2S + kg+lc+4];
            }
            #pragma unroll
            for (int ni = 0; ni < 8; ++ni) {
                int cI = wn*64 + ni*8 + lr;
                bfr[ni][0] = Bs[(kk+lc  )*BS2S + cI];
                bfr[ni][1] = Bs[(kk+lc+4)*BS2S + cI];
            }
            #pragma unroll
            for (int mi = 0; mi < 2; ++mi)
                #pragma unroll
                for (int ni = 0; ni < 8; ++ni)
                    mma8(acc[mi][ni], afr[mi], bfr[ni]);
        }
        __syncthreads();
    }

    // ---- final epilogue: + br2 -> d_out ----
    #pragma unroll
    for (int mi = 0; mi < 2; ++mi) {
        int gr = tm*BM2 + wm*32 + mi*16 + lr;
        #pragma unroll
        for (int ni = 0; ni < 8; ++ni) {
            int col = wn*64 + ni*8 + 2*lc;
            float b0 = br2[col], b1 = br2[col+1];
            float2 v;
            v.x = acc[mi][ni][0] + b0; v.y = acc[mi][ni][1] + b1;
            *(float2*)&out[(size_t)gr*DIM + col] = v;
            v.x = acc[mi][ni][2] + b0; v.y = acc[mi][ni][3] + b1;
            *(float2*)&out[(size_t)(gr+8)*DIM + col] = v;
        }
    }
}

// ============================================================
extern "C" void kernel_launch(void* const* d_in, const int* in_sizes, int n_in,
                              void* d_out, int out_size)
{
    const int*   tok = (const int*)  d_in[0];
    const float* E   = (const float*)d_in[1];
    const float* Wc1 = (const float*)d_in[2];
    const float* bc1 = (const float*)d_in[3];
    const float* Wc2 = (const float*)d_in[4];
    const float* bc2 = (const float*)d_in[5];
    const float* Wr1 = (const float*)d_in[6];
    const float* br1 = (const float*)d_in[7];
    const float* Wr2 = (const float*)d_in[8];
    const float* br2 = (const float*)d_in[9];
    float* out = (float*)d_out;

    // idempotent attribute sets — safe under graph capture
    cudaFuncSetAttribute(k_ctx, cudaFuncAttributeMaxDynamicSharedMemorySize, SM1_BYTES);
    cudaFuncSetAttribute(k_out, cudaFuncAttributeMaxDynamicSharedMemorySize, SM2_BYTES);

    k_prep<<<448, 256>>>(Wc1, Wr1, Wr2);
    k_fold<<<129, 256>>>(Wc2, bc2, Wr1, br1);
    k_ctx<<<NTOK/BM1, 256, SM1_BYTES>>>(tok, E, bc1);
    k_out<<<NTOK/BM2, 256, SM2_BYTES>>>(tok, E, br2, out);
}

// round 14
// speedup vs baseline: 1.3755x; 1.0339x over previous
#include <cuda_runtime.h>

#define BATCH 8
#define SEQ   4096
#define NTOK  (BATCH*SEQ)     // 32768
#define DIM   256
#define CWIN  5
#define KC    (CWIN*DIM)      // 1280
#define BK    32
#define HBK   16              // pipelined half-tile depth

// ---- device scratch (static globals: allowed; no runtime allocation) ----
__device__ unsigned g_at[(size_t)NTOK * DIM];  // relu(ctx@Wc1+bc1) as tf32 bits
__device__ unsigned g_Wfoldt[DIM * DIM];       // (Wc2 @ Wr1[256:512]) as tf32 bits
__device__ float    g_bfold[DIM];              // bc2 @ Wr1[256:512] + br1
__device__ unsigned g_Wc1t[KC * DIM];          // Wc1 as tf32 bits
__device__ unsigned g_Wr1t[DIM * DIM];         // Wr1 rows 0..255 as tf32 bits
__device__ unsigned g_Wr2t[DIM * DIM];         // Wr2 as tf32 bits

// ---- helpers ----
__device__ __forceinline__ unsigned f2tf(float f) {
    unsigned u;
    asm("cvt.rna.tf32.f32 %0, %1;" : "=r"(u) : "f"(f));
    return u;
}
__device__ __forceinline__ void mma8(float* c, const unsigned* a, const unsigned* b) {
    asm volatile(
        "mma.sync.aligned.m16n8k8.row.col.f32.tf32.tf32.f32 "
        "{%0,%1,%2,%3}, {%4,%5,%6,%7}, {%8,%9}, {%0,%1,%2,%3};\n"
        : "+f"(c[0]), "+f"(c[1]), "+f"(c[2]), "+f"(c[3])
        : "r"(a[0]), "r"(a[1]), "r"(a[2]), "r"(a[3]), "r"(b[0]), "r"(b[1]));
}
__device__ __forceinline__ void cpa16(unsigned saddr, const void* gptr) {
    asm volatile("cp.async.cg.shared.global [%0], [%1], 16;\n"
                 :: "r"(saddr), "l"(gptr) : "memory");
}
__device__ __forceinline__ void cpa_commit() {
    asm volatile("cp.async.commit_group;\n" ::: "memory");
}
__device__ __forceinline__ void cpa_wait0() {
    asm volatile("cp.async.wait_group 0;\n" ::: "memory");
}

// ============================================================
// Kernel P: one-time tf32 pre-conversion of weights.
// ============================================================
__global__ void k_prep(const float* __restrict__ Wc1,
                       const float* __restrict__ Wr1,
                       const float* __restrict__ Wr2)
{
    int t = blockIdx.x * 256 + threadIdx.x;   // float4 index
    const float4* src;
    uint4* dst;
    int off;
    if (t < 81920)       { src = (const float4*)Wc1; dst = (uint4*)g_Wc1t; off = t; }
    else if (t < 98304)  { src = (const float4*)Wr1; dst = (uint4*)g_Wr1t; off = t - 81920; }
    else                 { src = (const float4*)Wr2; dst = (uint4*)g_Wr2t; off = t - 98304; }
    float4 v = src[off];
    uint4 u; u.x = f2tf(v.x); u.y = f2tf(v.y); u.z = f2tf(v.z); u.w = f2tf(v.w);
    dst[off] = u;
}

// ============================================================
// Kernel 0: fold Wc2 into Wr1's h-half -> g_Wfoldt (tf32 bits).
// 128 blocks x 2 k-rows; Wc2 rows staged in SMEM; thread j streams coalesced
// Wr1 column loads, unroll 8 (few live regs => real MLP). Block 128 = bias.
// ============================================================
__global__ void k_fold(const float* __restrict__ Wc2, const float* __restrict__ bc2,
                       const float* __restrict__ Wr1, const float* __restrict__ br1)
{
    __shared__ float wc2s[2 * DIM];
    const int j = threadIdx.x;
    const int blk = blockIdx.x;
    if (blk < 128) {
        const int k0 = blk * 2;
        wc2s[j]       = Wc2[k0*DIM + j];
        wc2s[j + 256] = Wc2[k0*DIM + 256 + j];
        __syncthreads();
        float a0 = 0.f, a1 = 0.f;
        #pragma unroll 8
        for (int r = 0; r < DIM; ++r) {
            float w = Wr1[(DIM + r)*DIM + j];
            a0 = fmaf(wc2s[r],       w, a0);
            a1 = fmaf(wc2s[DIM + r], w, a1);
        }
        g_Wfoldt[(k0    )*DIM + j] = f2tf(a0);
        g_Wfoldt[(k0 + 1)*DIM + j] = f2tf(a1);
    } else {
        float acc = br1[j];
        #pragma unroll 8
        for (int r = 0; r < DIM; ++r)
            acc = fmaf(bc2[r], Wr1[(DIM + r)*DIM + j], acc);
        g_bfold[j] = acc;
    }
}

// ============================================================
// Kernel 1: a = relu(ctx @ Wc1 + bc1) -> g_at (tf32 bits)
// Halo staged once per block (measured win). NEW: Wc1 tile fills are
// cp.async-pipelined half-tiles (HBK=16, 2 half-buffers = SAME SMEM bytes
// as the old 32-row buffer) -- fill latency hidden under mma.
// BM=64, BN=256, 8 warps 2x4 (warp 32x64), occ 2. grid=512.
// ============================================================
#define BM1 64
#define ECH_S 260
#define BS1S  264
#define SM1_BYTES ((71*ECH_S + 2*HBK*BS1S + CWIN*BM1) * 4)   // 108,912 B

__global__ __launch_bounds__(256, 2) void k_ctx(
    const int* __restrict__ tok, const float* __restrict__ E,
    const float* __restrict__ bc1)
{
    extern __shared__ unsigned sm1[];
    unsigned* Ech = sm1;                              // 71 x 260
    unsigned* Bs  = sm1 + 71*ECH_S;                   // 2 bufs x 16 x 264
    int*     rmap = (int*)(sm1 + 71*ECH_S + 2*HBK*BS1S);
    __shared__ int heofs[70];

    const int tid = threadIdx.x;
    const int tm  = blockIdx.x;
    const int ts  = (tm * BM1) & (SEQ-1);
    const int b   = (tm * BM1) >> 12;
    const int hstart = max(0, ts - 4);
    const int hend   = min(SEQ - 1, ts + 65);

    if (tid < 70)
        heofs[tid] = tok[(b << 12) + min(hstart + tid, hend)] << 8;
    for (int t = tid; t < CWIN*BM1; t += 256) {
        int p = t >> 6;
        int r = t & (BM1-1);
        int i = ts + r;
        int end   = min(SEQ, i + 3);
        int start = max(0, i - 2);
        int idx = end - CWIN + p;
        rmap[t] = (idx >= start) ? (max(idx, 0) - hstart) : 70;
    }
    Ech[70*ECH_S + tid] = 0;
    __syncthreads();                       // heofs ready

    const unsigned bsb = (unsigned)__cvta_generic_to_shared(Bs);
    auto fillB = [&](int buf, int h) {
        const int k0 = h << 4;
        const unsigned sb = bsb + (unsigned)(buf * (HBK*BS1S*4));
        #pragma unroll
        for (int it = 0; it < 4; ++it) {
            int c = tid + it*256;               // 1024 uint4
            int kr = c >> 6, j4 = (c & 63) << 2;
            cpa16(sb + (kr*BS1S + j4)*4, g_Wc1t + (size_t)(k0 + kr)*DIM + j4);
        }
        cpa_commit();
    };

    fillB(0, 0);   // first B half-tile streams while we stage the halo

    // stage full 70x256 halo once (plain loads; needs cvt)
    for (int c = tid; c < 70*64; c += 256) {
        int q = c >> 6, f = (c & 63) << 2;
        float4 v = *(const float4*)(E + heofs[q] + f);
        uint4 u; u.x = f2tf(v.x); u.y = f2tf(v.y); u.z = f2tf(v.z); u.w = f2tf(v.w);
        *(uint4*)&Ech[q*ECH_S + f] = u;
    }

    const int warp = tid >> 5, lane = tid & 31;
    const int wm = warp & 1, wn = warp >> 1;
    const int lr = lane >> 2, lc = lane & 3;

    float acc[2][8][4];
    #pragma unroll
    for (int mi = 0; mi < 2; ++mi)
        #pragma unroll
        for (int ni = 0; ni < 8; ++ni)
            #pragma unroll
            for (int q = 0; q < 4; ++q) acc[mi][ni][q] = 0.f;

    // pipelined mainloop: 80 half-tiles, ONE barrier each
    for (int h = 0; h < KC/HBK; ++h) {
        cpa_wait0();
        __syncthreads();                  // publishes buf[h&1] (+halo on h=0)
        if (h + 1 < KC/HBK) fillB((h+1)&1, h+1);

        const unsigned* Bc = Bs + (h&1)*(HBK*BS1S);
        const int k0 = h << 4;
        const int p  = k0 >> 8;
        const int kp = k0 & 255;
        int rm[2][2];
        rm[0][0] = rmap[p*BM1 + wm*32 + lr];
        rm[0][1] = rmap[p*BM1 + wm*32 + lr + 8];
        rm[1][0] = rmap[p*BM1 + wm*32 + 16 + lr];
        rm[1][1] = rmap[p*BM1 + wm*32 + 24 + lr];

        #pragma unroll
        for (int kk = 0; kk < HBK; kk += 8) {
            unsigned afr[2][4], bfr[8][2];
            #pragma unroll
            for (int mi = 0; mi < 2; ++mi) {
                afr[mi][0] = Ech[rm[mi][0]*ECH_S + kp+kk+lc  ];
                afr[mi][1] = Ech[rm[mi][1]*ECH_S + kp+kk+lc  ];
                afr[mi][2] = Ech[rm[mi][0]*ECH_S + kp+kk+lc+4];
                afr[mi][3] = Ech[rm[mi][1]*ECH_S + kp+kk+lc+4];
            }
            #pragma unroll
            for (int ni = 0; ni < 8; ++ni) {
                int cI = wn*64 + ni*8 + lr;
                bfr[ni][0] = Bc[(kk+lc  )*BS1S + cI];
                bfr[ni][1] = Bc[(kk+lc+4)*BS1S + cI];
            }
            #pragma unroll
            for (int mi = 0; mi < 2; ++mi)
                #pragma unroll
                for (int ni = 0; ni < 8; ++ni)
                    mma8(acc[mi][ni], afr[mi], bfr[ni]);
        }
    }

    // epilogue: relu(acc + bc1) -> g_at (tf32 bits)
    #pragma unroll
    for (int mi = 0; mi < 2; ++mi) {
        int r0 = tm*BM1 + wm*32 + mi*16 + lr;
        #pragma unroll
        for (int ni = 0; ni < 8; ++ni) {
            int col = wn*64 + ni*8 + 2*lc;
            float b0 = bc1[col], b1 = bc1[col+1];
            uint2 v0, v1;
            v0.x = f2tf(fmaxf(acc[mi][ni][0] + b0, 0.f));
            v0.y = f2tf(fmaxf(acc[mi][ni][1] + b1, 0.f));
            v1.x = f2tf(fmaxf(acc[mi][ni][2] + b0, 0.f));
            v1.y = f2tf(fmaxf(acc[mi][ni][3] + b1, 0.f));
            *(uint2*)&g_at[(size_t)r0*DIM + col]     = v0;
            *(uint2*)&g_at[(size_t)(r0+8)*DIM + col] = v1;
        }
    }
}

// ============================================================
// Kernel 2 (fused): t = [a | static] @ [Wfold ; Wr1a] -> tanh -> @ Wr2
// Phase-1 k-order reordered (commutative): static-E half (cvt, synchronous,
// unchanged) FIRST, then the raw-copy g_at/Wfold half cp.async-pipelined;
// phase-2 Wr2 fills also pipelined. SMEM 110,848 B, occ 2 forced.
// grid = 512
// ============================================================
#define BM2 64
#define BS2S 264
#define US2S 260
#define AS1A_S 36
#define AS1B_S 20
#define SM_AS 0
#define AS_WORDS 2560                            // max(64*36, 2*64*20)
#define SM_BS AS_WORDS                           // 2560
#define BS_WORDS (2*HBK*BS2S)                    // 8448
#define SM_US (SM_BS + BS_WORDS)                 // 11008
#define SM_TK (SM_US + 64*US2S)                  // 27648
#define SM2_BYTES ((SM_TK + 64) * 4)             // 110,848 B

__global__ __launch_bounds__(256, 2) void k_out(
    const int* __restrict__ tok, const float* __restrict__ E,
    const float* __restrict__ br2, float* __restrict__ out)
{
    extern __shared__ unsigned smu[];
    unsigned* As = smu + SM_AS;
    unsigned* Bs = smu + SM_BS;
    unsigned* Us = smu + SM_US;
    int*      st = (int*)(smu + SM_TK);

    const int tid = threadIdx.x;
    const int tm  = blockIdx.x;

    for (int r = tid; r < BM2; r += 256)
        st[r] = tok[tm*BM2 + r] * DIM;

    const int warp = tid >> 5, lane = tid & 31;
    const int wm = warp & 1, wn = warp >> 1;
    const int lr = lane >> 2, lc = lane & 3;

    const unsigned asb = (unsigned)__cvta_generic_to_shared(As);
    const unsigned bsb = (unsigned)__cvta_generic_to_shared(Bs);

    float acc[2][8][4];
    #pragma unroll
    for (int mi = 0; mi < 2; ++mi)
        #pragma unroll
        for (int ni = 0; ni < 8; ++ni)
            #pragma unroll
            for (int q = 0; q < 4; ++q) acc[mi][ni][q] = 0.f;

    __syncthreads();   // st[] ready

    // ---- phase 1a (synchronous): k = 256..511, A = static E (cvt), B = Wr1a
    for (int k0 = 0; k0 < DIM; k0 += BK) {
        #pragma unroll
        for (int it = 0; it < 2; ++it) {
            int f4 = tid + it*256;
            int r  = f4 >> 3;
            int cg = (f4 & 7) << 2;
            float4 v = *(const float4*)(E + st[r] + k0 + cg);
            uint4 u; u.x = f2tf(v.x); u.y = f2tf(v.y); u.z = f2tf(v.z); u.w = f2tf(v.w);
            *(uint4*)&As[r*AS1A_S + cg] = u;
        }
        #pragma unroll
        for (int it = 0; it < 8; ++it) {
            int f4 = tid + it*256;
            int kr = f4 >> 6;
            int jc = (f4 & 63) << 2;
            *(uint4*)&Bs[kr*BS2S + jc] =
                *(const uint4*)(g_Wr1t + (size_t)(k0 + kr)*DIM + jc);
        }
        __syncthreads();

        #pragma unroll
        for (int kk = 0; kk < BK; kk += 8) {
            unsigned afr[2][4], bfr[8][2];
            #pragma unroll
            for (int mi = 0; mi < 2; ++mi) {
                int r = wm*32 + mi*16 + lr;
                afr[mi][0] = As[ r   *AS1A_S + kk+lc  ];
                afr[mi][1] = As[(r+8)*AS1A_S + kk+lc  ];
                afr[mi][2] = As[ r   *AS1A_S + kk+lc+4];
                afr[mi][3] = As[(r+8)*AS1A_S + kk+lc+4];
            }
            #pragma unroll
            for (int ni = 0; ni < 8; ++ni) {
                int cI = wn*64 + ni*8 + lr;
                bfr[ni][0] = Bs[(kk+lc  )*BS2S + cI];
                bfr[ni][1] = Bs[(kk+lc+4)*BS2S + cI];
            }
            #pragma unroll
            for (int mi = 0; mi < 2; ++mi)
                #pragma unroll
                for (int ni = 0; ni < 8; ++ni)
                    mma8(acc[mi][ni], afr[mi], bfr[ni]);
        }
        __syncthreads();
    }

    // ---- phase 1b (pipelined): k = 0..255, A = g_at, B = Wfold (raw bits)
    auto fill1b = [&](int buf, int h) {
        const int k0 = h << 4;
        {
            int r = tid >> 2, c4 = (tid & 3) << 2;
            cpa16(asb + (buf*(BM2*AS1B_S) + r*AS1B_S + c4)*4,
                  g_at + (size_t)(tm*BM2 + r)*DIM + k0 + c4);
        }
        #pragma unroll
        for (int it = 0; it < 4; ++it) {
            int c = tid + it*256;
            int kr = c >> 6, j4 = (c & 63) << 2;
            cpa16(bsb + (buf*(HBK*BS2S) + kr*BS2S + j4)*4,
                  g_Wfoldt + (size_t)(k0 + kr)*DIM + j4);
        }
        cpa_commit();
    };

    fill1b(0, 0);
    for (int h = 0; h < DIM/HBK; ++h) {
        cpa_wait0();
        __syncthreads();
        if (h + 1 < DIM/HBK) fill1b((h+1)&1, h+1);

        const unsigned* Ac = As + (h&1)*(BM2*AS1B_S);
        const unsigned* Bc = Bs + (h&1)*(HBK*BS2S);
        #pragma unroll
        for (int kk = 0; kk < HBK; kk += 8) {
            unsigned afr[2][4], bfr[8][2];
            #pragma unroll
            for (int mi = 0; mi < 2; ++mi) {
                int r = wm*32 + mi*16 + lr;
                afr[mi][0] = Ac[ r   *AS1B_S + kk+lc  ];
                afr[mi][1] = Ac[(r+8)*AS1B_S + kk+lc  ];
                afr[mi][2] = Ac[ r   *AS1B_S + kk+lc+4];
                afr[mi][3] = Ac[(r+8)*AS1B_S + kk+lc+4];
            }
            #pragma unroll
            for (int ni = 0; ni < 8; ++ni) {
                int cI = wn*64 + ni*8 + lr;
                bfr[ni][0] = Bc[(kk+lc  )*BS2S + cI];
                bfr[ni][1] = Bc[(kk+lc+4)*BS2S + cI];
            }
            #pragma unroll
            for (int mi = 0; mi < 2; ++mi)
                #pragma unroll
                for (int ni = 0; ni < 8; ++ni)
                    mma8(acc[mi][ni], afr[mi], bfr[ni]);
        }
    }

    // ---- tanh epilogue -> Us (tf32); reset accumulators ----
    #pragma unroll
    for (int mi = 0; mi < 2; ++mi) {
        int r = wm*32 + mi*16 + lr;
        #pragma unroll
        for (int ni = 0; ni < 8; ++ni) {
            int col = wn*64 + ni*8 + 2*lc;
            float b0 = g_bfold[col], b1 = g_bfold[col+1];
            Us[ r   *US2S + col  ] = f2tf(tanhf(acc[mi][ni][0] + b0));
            Us[ r   *US2S + col+1] = f2tf(tanhf(acc[mi][ni][1] + b1));
            Us[(r+8)*US2S + col  ] = f2tf(tanhf(acc[mi][ni][2] + b0));
            Us[(r+8)*US2S + col+1] = f2tf(tanhf(acc[mi][ni][3] + b1));
            acc[mi][ni][0] = 0.f; acc[mi][ni][1] = 0.f;
            acc[mi][ni][2] = 0.f; acc[mi][ni][3] = 0.f;
        }
    }

    // ---- phase 2 (pipelined): out = Us @ Wr2 + br2, K = 256 ----
    auto fill2 = [&](int buf, int h) {
        const int k0 = h << 4;
        #pragma unroll
        for (int it = 0; it < 4; ++it) {
            int c = tid + it*256;
            int kr = c >> 6, j4 = (c & 63) << 2;
            cpa16(bsb + (buf*(HBK*BS2S) + kr*BS2S + j4)*4,
                  g_Wr2t + (size_t)(k0 + kr)*DIM + j4);
        }
        cpa_commit();
    };

    fill2(0, 0);
    for (int h = 0; h < DIM/HBK; ++h) {
        cpa_wait0();
        __syncthreads();                 // publishes B buf + Us (first iter)
        if (h + 1 < DIM/HBK) fill2((h+1)&1, h+1);

        const unsigned* Bc = Bs + (h&1)*(HBK*BS2S);
        const int kb = h << 4;
        #pragma unroll
        for (int kk = 0; kk < HBK; kk += 8) {
            int kg = kb + kk;
            unsigned afr[2][4], bfr[8][2];
            #pragma unroll
            for (int mi = 0; mi < 2; ++mi) {
                int r = wm*32 + mi*16 + lr;
                afr[mi][0] = Us[ r   *US2S + kg+lc  ];
                afr[mi][1] = Us[(r+8)*US2S + kg+lc  ];
                afr[mi][2] = Us[ r   *US2S + kg+lc+4];
                afr[mi][3] = Us[(r+8)*US2S + kg+lc+4];
            }
            #pragma unroll
            for (int ni = 0; ni < 8; ++ni) {
                int cI = wn*64 + ni*8 + lr;
                bfr[ni][0] = Bc[(kk+lc  )*BS2S + cI];
                bfr[ni][1] = Bc[(kk+lc+4)*BS2S + cI];
            }
            #pragma unroll
            for (int mi = 0; mi < 2; ++mi)
                #pragma unroll
                for (int ni = 0; ni < 8; ++ni)
                    mma8(acc[mi][ni], afr[mi], bfr[ni]);
        }
    }

    // ---- final epilogue: + br2 -> d_out ----
    #pragma unroll
    for (int mi = 0; mi < 2; ++mi) {
        int gr = tm*BM2 + wm*32 + mi*16 + lr;
        #pragma unroll
        for (int ni = 0; ni < 8; ++ni) {
            int col = wn*64 + ni*8 + 2*lc;
            float b0 = br2[col], b1 = br2[col+1];
            float2 v;
            v.x = acc[mi][ni][0] + b0; v.y = acc[mi][ni][1] + b1;
            *(float2*)&out[(size_t)gr*DIM + col] = v;
            v.x = acc[mi][ni][2] + b0; v.y = acc[mi][ni][3] + b1;
            *(float2*)&out[(size_t)(gr+8)*DIM + col] = v;
        }
    }
}

// ============================================================
extern "C" void kernel_launch(void* const* d_in, const int* in_sizes, int n_in,
                              void* d_out, int out_size)
{
    const int*   tok = (const int*)  d_in[0];
    const float* E   = (const float*)d_in[1];
    const float* Wc1 = (const float*)d_in[2];
    const float* bc1 = (const float*)d_in[3];
    const float* Wc2 = (const float*)d_in[4];
    const float* bc2 = (const float*)d_in[5];
    const float* Wr1 = (const float*)d_in[6];
    const float* br1 = (const float*)d_in[7];
    const float* Wr2 = (const float*)d_in[8];
    const float* br2 = (const float*)d_in[9];
    float* out = (float*)d_out;

    cudaFuncSetAttribute(k_ctx, cudaFuncAttributeMaxDynamicSharedMemorySize, SM1_BYTES);
    cudaFuncSetAttribute(k_out, cudaFuncAttributeMaxDynamicSharedMemorySize, SM2_BYTES);

    k_prep<<<448, 256>>>(Wc1, Wr1, Wr2);
    k_fold<<<129, 256>>>(Wc2, bc2, Wr1, br1);
    k_ctx<<<NTOK/BM1, 256, SM1_BYTES>>>(tok, E, bc1);
    k_out<<<NTOK/BM2, 256, SM2_BYTES>>>(tok, E, br2, out);
}